// round 4
// baseline (speedup 1.0000x reference)
#include <cuda_runtime.h>

// Problem constants (fixed shapes from setup_inputs)
#define B_   16
#define T_   5
#define H_   256
#define W_   256
#define CIN  3
#define F_   8
#define GC   32            // 4*F gate channels
#define TILE 16
#define HALO (TILE + 2)

#define NSTATE ((size_t)B_ * H_ * W_ * F_)

// State buffers: h double-buffered (halo reads cross block boundaries),
// c single-buffered (strictly pointwise, in-place is race-free).
__device__ float g_h0[NSTATE];
__device__ float g_h1[NSTATE];
__device__ float g_c [NSTATE];

// ---------- fast-but-safe activations ----------
__device__ __forceinline__ float sigm(float x) {
    // exp(-x) -> inf for very negative x is fine: 1/inf -> 0 via approx div.
    float e = __expf(-x);
    return __fdividef(1.0f, 1.0f + e);
}
__device__ __forceinline__ float tanh_(float x) {
    // Work on |x| so exp argument is always <= 0 (no inf/NaN), restore sign.
    float ax = fabsf(x);
    float e  = __expf(-2.0f * ax);
    float t  = __fdividef(1.0f - e, 1.0f + e);
    return copysignf(t, x);
}

// ---------- packed fp32x2 helpers (ptxas will not auto-fuse these) ----------
__device__ __forceinline__ unsigned long long pack2(float a) {
    unsigned long long r;
    asm("mov.b64 %0, {%1, %1};" : "=l"(r) : "f"(a));
    return r;
}
__device__ __forceinline__ void fma2(unsigned long long& d,
                                     unsigned long long a,
                                     unsigned long long b) {
    asm("fma.rn.f32x2 %0, %1, %2, %0;" : "+l"(d) : "l"(a), "l"(b));
}
__device__ __forceinline__ void unpack2(unsigned long long v, float& lo, float& hi) {
    unsigned lu, hu;
    asm("mov.b64 {%0, %1}, %2;" : "=r"(lu), "=r"(hu) : "l"(v));
    lo = __uint_as_float(lu);
    hi = __uint_as_float(hu);
}

// One ConvLSTM timestep, fused gates; LAST additionally fuses BN+LeakyReLU+Dense.
template <bool FIRST, bool LAST>
__global__ __launch_bounds__(256)
void convlstm_step(const float* __restrict__ x_all, int t,
                   const float* __restrict__ wk,    // [3,3,CIN,GC]
                   const float* __restrict__ wr,    // [3,3,F,GC]
                   const float* __restrict__ bias,  // [GC]
                   const float* __restrict__ h_in,
                   float*       __restrict__ h_out,
                   const float* __restrict__ gamma,
                   const float* __restrict__ beta,
                   const float* __restrict__ mean,
                   const float* __restrict__ var,
                   const float* __restrict__ dw,    // [F,2]
                   const float* __restrict__ db,    // [2]
                   float*       __restrict__ out)   // [B,H,W,2]
{
    __shared__ __align__(16) float wks[27 * GC];        // 3.4 KB
    __shared__ __align__(16) float wrs[72 * GC];        // 9.2 KB
    __shared__ __align__(16) float bs [GC];
    __shared__ float              xs [HALO * HALO * CIN]; // 3.9 KB
    __shared__ __align__(16) float hs [HALO * HALO * F_]; // 10.4 KB

    const int tx  = threadIdx.x, ty = threadIdx.y;
    const int tid = ty * TILE + tx;
    const int bx  = blockIdx.x, by = blockIdx.y, b = blockIdx.z;
    const int gx0 = bx * TILE - 1, gy0 = by * TILE - 1;

    // -- stage weights + bias --
    for (int i = tid; i < 27 * GC; i += 256) wks[i] = wk[i];
    if (!FIRST)
        for (int i = tid; i < 72 * GC; i += 256) wrs[i] = wr[i];
    if (tid < GC) bs[tid] = bias[tid];

    // -- stage x tile (with zero halo) --
    const float* xt = x_all + (size_t)(b * T_ + t) * H_ * W_ * CIN;
    for (int i = tid; i < HALO * HALO; i += 256) {
        int iy = i / HALO, ix = i % HALO;
        int gy = gy0 + iy, gx = gx0 + ix;
        float v0 = 0.f, v1 = 0.f, v2 = 0.f;
        if ((unsigned)gy < H_ && (unsigned)gx < W_) {
            const float* p = xt + ((size_t)gy * W_ + gx) * CIN;
            v0 = p[0]; v1 = p[1]; v2 = p[2];
        }
        xs[i * CIN + 0] = v0;
        xs[i * CIN + 1] = v1;
        xs[i * CIN + 2] = v2;
    }

    // -- stage h tile (with zero halo), vectorized float4 --
    if (!FIRST) {
        const float* hb = h_in + (size_t)b * H_ * W_ * F_;
        for (int i = tid; i < HALO * HALO; i += 256) {
            int iy = i / HALO, ix = i % HALO;
            int gy = gy0 + iy, gx = gx0 + ix;
            float4 a = make_float4(0.f, 0.f, 0.f, 0.f);
            float4 c = make_float4(0.f, 0.f, 0.f, 0.f);
            if ((unsigned)gy < H_ && (unsigned)gx < W_) {
                const float4* p = (const float4*)(hb + ((size_t)gy * W_ + gx) * F_);
                a = p[0]; c = p[1];
            }
            float4* d = (float4*)&hs[i * F_];
            d[0] = a; d[1] = c;
        }
    }
    __syncthreads();

    // -- 16 packed accumulators = 32 gate channels, init from bias --
    unsigned long long acc[16];
    {
        const ulonglong2* bp = (const ulonglong2*)bs;
#pragma unroll
        for (int j = 0; j < 8; j++) {
            ulonglong2 v = bp[j];
            acc[2 * j]     = v.x;
            acc[2 * j + 1] = v.y;
        }
    }

    // -- input conv: 27 taps x 32 channels --
#pragma unroll
    for (int ky = 0; ky < 3; ky++) {
#pragma unroll
        for (int kx = 0; kx < 3; kx++) {
            const float* xp = &xs[((ty + ky) * HALO + tx + kx) * CIN];
            const int pb = (ky * 3 + kx) * CIN;
#pragma unroll
            for (int ci = 0; ci < CIN; ci++) {
                unsigned long long a2 = pack2(xp[ci]);
                const ulonglong2* w = (const ulonglong2*)&wks[(pb + ci) * GC];
#pragma unroll
                for (int j = 0; j < 8; j++) {
                    ulonglong2 wv = w[j];
                    fma2(acc[2 * j],     a2, wv.x);
                    fma2(acc[2 * j + 1], a2, wv.y);
                }
            }
        }
    }

    // -- recurrent conv: 72 taps x 32 channels --
    if (!FIRST) {
#pragma unroll
        for (int ky = 0; ky < 3; ky++) {
#pragma unroll
            for (int kx = 0; kx < 3; kx++) {
                const float* hp = &hs[((ty + ky) * HALO + tx + kx) * F_];
                const int pb = (ky * 3 + kx) * F_;
#pragma unroll 4
                for (int ci = 0; ci < F_; ci++) {
                    unsigned long long a2 = pack2(hp[ci]);
                    const ulonglong2* w = (const ulonglong2*)&wrs[(pb + ci) * GC];
#pragma unroll
                    for (int j = 0; j < 8; j++) {
                        ulonglong2 wv = w[j];
                        fma2(acc[2 * j],     a2, wv.x);
                        fma2(acc[2 * j + 1], a2, wv.y);
                    }
                }
            }
        }
    }

    // -- gates --
    float z[32];
#pragma unroll
    for (int j = 0; j < 16; j++) unpack2(acc[j], z[2 * j], z[2 * j + 1]);

    const int gy = by * TILE + ty, gx = bx * TILE + tx;
    const size_t pix = ((size_t)b * H_ + gy) * W_ + gx;

    float cprev[F_];
    if (!FIRST) {
        const float4* cp = (const float4*)&g_c[pix * F_];
        float4 c0 = cp[0], c1 = cp[1];
        cprev[0] = c0.x; cprev[1] = c0.y; cprev[2] = c0.z; cprev[3] = c0.w;
        cprev[4] = c1.x; cprev[5] = c1.y; cprev[6] = c1.z; cprev[7] = c1.w;
    }

    float hv[F_], cv[F_];
#pragma unroll
    for (int f = 0; f < F_; f++) {
        float ig = sigm(z[f]);               // input gate
        float gg = tanh_(z[16 + f]);         // candidate
        float og = sigm(z[24 + f]);          // output gate
        float c;
        if (FIRST) {
            c = ig * gg;                     // c_prev = 0, forget term vanishes
        } else {
            float fg = sigm(z[8 + f]);       // forget gate
            c = fg * cprev[f] + ig * gg;
        }
        cv[f] = c;
        hv[f] = og * tanh_(c);
    }

    if (!LAST) {
        float4* cd = (float4*)&g_c[pix * F_];
        cd[0] = make_float4(cv[0], cv[1], cv[2], cv[3]);
        cd[1] = make_float4(cv[4], cv[5], cv[6], cv[7]);
        float4* hd = (float4*)(h_out + pix * F_);
        hd[0] = make_float4(hv[0], hv[1], hv[2], hv[3]);
        hd[1] = make_float4(hv[4], hv[5], hv[6], hv[7]);
    } else {
        // BN (inference, eps=1e-3) + LeakyReLU(0.3) + Dense(2), fused.
        float o0 = db[0], o1 = db[1];
#pragma unroll
        for (int f = 0; f < F_; f++) {
            float xn = (hv[f] - mean[f]) * rsqrtf(var[f] + 1e-3f) * gamma[f] + beta[f];
            xn = (xn >= 0.f) ? xn : 0.3f * xn;
            o0 += xn * dw[2 * f + 0];
            o1 += xn * dw[2 * f + 1];
        }
        *(float2*)(out + pix * 2) = make_float2(o0, o1);
    }
}

extern "C" void kernel_launch(void* const* d_in, const int* in_sizes, int n_in,
                              void* d_out, int out_size)
{
    (void)in_sizes; (void)n_in; (void)out_size;
    const float* x     = (const float*)d_in[0];
    const float* wk    = (const float*)d_in[1];
    const float* wr    = (const float*)d_in[2];
    const float* bias  = (const float*)d_in[3];
    const float* gamma = (const float*)d_in[4];
    const float* beta  = (const float*)d_in[5];
    const float* mean  = (const float*)d_in[6];
    const float* var   = (const float*)d_in[7];
    const float* dw    = (const float*)d_in[8];
    const float* db    = (const float*)d_in[9];
    float* out         = (float*)d_out;

    float *h0 = nullptr, *h1 = nullptr;
    cudaGetSymbolAddress((void**)&h0, g_h0);
    cudaGetSymbolAddress((void**)&h1, g_h1);

    dim3 grid(W_ / TILE, H_ / TILE, B_);
    dim3 block(TILE, TILE, 1);

    // t=0: h=c=0 (FIRST), writes h0 + c
    convlstm_step<true,  false><<<grid, block>>>(x, 0, wk, wr, bias, h0, h0,
                                                 gamma, beta, mean, var, dw, db, out);
    // t=1..3: ping-pong h buffers, c in place
    convlstm_step<false, false><<<grid, block>>>(x, 1, wk, wr, bias, h0, h1,
                                                 gamma, beta, mean, var, dw, db, out);
    convlstm_step<false, false><<<grid, block>>>(x, 2, wk, wr, bias, h1, h0,
                                                 gamma, beta, mean, var, dw, db, out);
    convlstm_step<false, false><<<grid, block>>>(x, 3, wk, wr, bias, h0, h1,
                                                 gamma, beta, mean, var, dw, db, out);
    // t=4: LAST — fused BN + LeakyReLU + Dense epilogue straight to d_out
    convlstm_step<false, true ><<<grid, block>>>(x, 4, wk, wr, bias, h1, h1,
                                                 gamma, beta, mean, var, dw, db, out);
}

// round 9
// speedup vs baseline: 1.5854x; 1.5854x over previous
#include <cuda_runtime.h>

// Problem constants (fixed shapes from setup_inputs)
#define B_    16
#define T_    5
#define H_    256
#define W_    256
#define CIN   3
#define F_    8
#define GC    32            // 4*F gate channels
#define TXD   32            // block x-dim (one warp = one row)
#define TYD   8             // block y-dim
#define TILEY 16            // rows per block (2 pixels per thread in y)
#define HX    34            // 32 + halo
#define HY    18            // 16 + halo
#define PLANE (HX * HY)     // 612

#define NSTATE ((size_t)B_ * H_ * W_ * F_)

// State buffers: h double-buffered (halo reads cross block boundaries),
// c single-buffered (strictly pointwise, in-place is race-free).
__device__ float g_h0[NSTATE];
__device__ float g_h1[NSTATE];
__device__ float g_c [NSTATE];

// ---------- fast-but-safe activations ----------
__device__ __forceinline__ float sigm(float x) {
    float e = __expf(-x);
    return __fdividef(1.0f, 1.0f + e);
}
__device__ __forceinline__ float tanh_(float x) {
    float ax = fabsf(x);
    float e  = __expf(-2.0f * ax);
    float t  = __fdividef(1.0f - e, 1.0f + e);
    return copysignf(t, x);
}

// ---------- packed fp32x2 helpers (ptxas will not auto-fuse these) ----------
__device__ __forceinline__ unsigned long long pack2(float a) {
    unsigned long long r;
    asm("mov.b64 %0, {%1, %1};" : "=l"(r) : "f"(a));
    return r;
}
__device__ __forceinline__ void fma2(unsigned long long& d,
                                     unsigned long long a,
                                     unsigned long long b) {
    asm("fma.rn.f32x2 %0, %1, %2, %0;" : "+l"(d) : "l"(a), "l"(b));
}
__device__ __forceinline__ void unpack2(unsigned long long v, float& lo, float& hi) {
    unsigned lu, hu;
    asm("mov.b64 {%0, %1}, %2;" : "=r"(lu), "=r"(hu) : "l"(v));
    lo = __uint_as_float(lu);
    hi = __uint_as_float(hu);
}

// One ConvLSTM timestep, 2 pixels/thread, SoA activation tiles.
// LAST additionally fuses BN+LeakyReLU+Dense.
template <bool FIRST, bool LAST>
__global__ __launch_bounds__(256, 2)
void convlstm_step(const float* __restrict__ x_all, int t,
                   const float* __restrict__ wk,    // [3,3,CIN,GC]
                   const float* __restrict__ wr,    // [3,3,F,GC]
                   const float* __restrict__ bias,  // [GC]
                   const float* __restrict__ h_in,
                   float*       __restrict__ h_out,
                   const float* __restrict__ gamma,
                   const float* __restrict__ beta,
                   const float* __restrict__ mean,
                   const float* __restrict__ var,
                   const float* __restrict__ dw,    // [F,2]
                   const float* __restrict__ db,    // [2]
                   float*       __restrict__ out)   // [B,H,W,2]
{
    // SoA activation planes: lane stride 1 within a warp row -> conflict-free LDS
    __shared__ float xs[CIN * PLANE];                 // 7.3 KB
    __shared__ float hs[F_  * PLANE];                 // 19.6 KB
    __shared__ __align__(16) float wks[27 * GC];      // 3.4 KB
    __shared__ __align__(16) float wrs[72 * GC];      // 9.2 KB
    __shared__ __align__(16) float bs [GC];

    const int tx  = threadIdx.x, ty = threadIdx.y;
    const int tid = ty * TXD + tx;
    const int bx  = blockIdx.x, by = blockIdx.y, b = blockIdx.z;
    const int gx0 = bx * TXD  - 1;
    const int gy0 = by * TILEY - 1;

    // -- stage weights + bias --
    for (int i = tid; i < 27 * GC; i += 256) wks[i] = wk[i];
    if (!FIRST)
        for (int i = tid; i < 72 * GC; i += 256) wrs[i] = wr[i];
    if (tid < GC) bs[tid] = bias[tid];

    // -- stage x and h halo tiles, transposing AoS(gmem) -> SoA(smem) --
    const float* xt = x_all + (size_t)(b * T_ + t) * H_ * W_ * CIN;
    const float* hb = FIRST ? nullptr : h_in + (size_t)b * H_ * W_ * F_;
    for (int i = tid; i < PLANE; i += 256) {
        int iy = i / HX, ix = i % HX;
        int gy = gy0 + iy, gx = gx0 + ix;
        bool in = ((unsigned)gy < H_) && ((unsigned)gx < W_);
        // x: 3 channels
        float v0 = 0.f, v1 = 0.f, v2 = 0.f;
        if (in) {
            const float* p = xt + ((size_t)gy * W_ + gx) * CIN;
            v0 = p[0]; v1 = p[1]; v2 = p[2];
        }
        xs[0 * PLANE + i] = v0;
        xs[1 * PLANE + i] = v1;
        xs[2 * PLANE + i] = v2;
        // h: 8 channels
        if (!FIRST) {
            float4 a = make_float4(0.f, 0.f, 0.f, 0.f);
            float4 c = make_float4(0.f, 0.f, 0.f, 0.f);
            if (in) {
                const float4* p = (const float4*)(hb + ((size_t)gy * W_ + gx) * F_);
                a = p[0]; c = p[1];
            }
            hs[0 * PLANE + i] = a.x; hs[1 * PLANE + i] = a.y;
            hs[2 * PLANE + i] = a.z; hs[3 * PLANE + i] = a.w;
            hs[4 * PLANE + i] = c.x; hs[5 * PLANE + i] = c.y;
            hs[6 * PLANE + i] = c.z; hs[7 * PLANE + i] = c.w;
        }
    }
    __syncthreads();

    // -- 2 pixels x 16 packed accumulators (32 gate channels each) --
    unsigned long long accA[16], accB[16];
    {
        const ulonglong2* bp = (const ulonglong2*)bs;
#pragma unroll
        for (int j = 0; j < 8; j++) {
            ulonglong2 v = bp[j];
            accA[2 * j] = v.x; accA[2 * j + 1] = v.y;
            accB[2 * j] = v.x; accB[2 * j + 1] = v.y;
        }
    }

    // -- input conv: 27 taps x 32 channels, 2 pixels --
#pragma unroll
    for (int ky = 0; ky < 3; ky++) {
#pragma unroll
        for (int kx = 0; kx < 3; kx++) {
            const int base0 = (ty + ky) * HX + tx + kx;       // pixel A (row ty)
            const int base1 = base0 + 8 * HX;                 // pixel B (row ty+8)
            const int pb = (ky * 3 + kx) * CIN;
#pragma unroll
            for (int ci = 0; ci < CIN; ci++) {
                unsigned long long A0 = pack2(xs[ci * PLANE + base0]);
                unsigned long long A1 = pack2(xs[ci * PLANE + base1]);
                const ulonglong2* w = (const ulonglong2*)&wks[(pb + ci) * GC];
#pragma unroll
                for (int j = 0; j < 8; j++) {
                    ulonglong2 wv = w[j];
                    fma2(accA[2 * j],     A0, wv.x);
                    fma2(accA[2 * j + 1], A0, wv.y);
                    fma2(accB[2 * j],     A1, wv.x);
                    fma2(accB[2 * j + 1], A1, wv.y);
                }
            }
        }
    }

    // -- recurrent conv: 72 taps x 32 channels, 2 pixels --
    if (!FIRST) {
#pragma unroll
        for (int ky = 0; ky < 3; ky++) {
#pragma unroll
            for (int kx = 0; kx < 3; kx++) {
                const int base0 = (ty + ky) * HX + tx + kx;
                const int base1 = base0 + 8 * HX;
                const int pb = (ky * 3 + kx) * F_;
#pragma unroll
                for (int ci = 0; ci < F_; ci++) {
                    unsigned long long A0 = pack2(hs[ci * PLANE + base0]);
                    unsigned long long A1 = pack2(hs[ci * PLANE + base1]);
                    const ulonglong2* w = (const ulonglong2*)&wrs[(pb + ci) * GC];
#pragma unroll
                    for (int j = 0; j < 8; j++) {
                        ulonglong2 wv = w[j];
                        fma2(accA[2 * j],     A0, wv.x);
                        fma2(accA[2 * j + 1], A0, wv.y);
                        fma2(accB[2 * j],     A1, wv.x);
                        fma2(accB[2 * j + 1], A1, wv.y);
                    }
                }
            }
        }
    }

    // -- gates + state update + (optional) fused BN/LeakyReLU/Dense, per pixel --
    const int gx = bx * TXD + tx;
#pragma unroll
    for (int p = 0; p < 2; p++) {
        unsigned long long* acc = p ? accB : accA;
        const int gy = by * TILEY + ty + p * 8;
        const size_t pix = ((size_t)b * H_ + gy) * W_ + gx;

        float z[32];
#pragma unroll
        for (int j = 0; j < 16; j++) unpack2(acc[j], z[2 * j], z[2 * j + 1]);

        float cprev[F_];
        if (!FIRST) {
            const float4* cp = (const float4*)&g_c[pix * F_];
            float4 c0 = cp[0], c1 = cp[1];
            cprev[0] = c0.x; cprev[1] = c0.y; cprev[2] = c0.z; cprev[3] = c0.w;
            cprev[4] = c1.x; cprev[5] = c1.y; cprev[6] = c1.z; cprev[7] = c1.w;
        }

        float hv[F_], cv[F_];
#pragma unroll
        for (int f = 0; f < F_; f++) {
            float ig = sigm(z[f]);               // input gate
            float gg = tanh_(z[16 + f]);         // candidate
            float og = sigm(z[24 + f]);          // output gate
            float c;
            if (FIRST) {
                c = ig * gg;                     // c_prev = 0
            } else {
                float fg = sigm(z[8 + f]);       // forget gate
                c = fg * cprev[f] + ig * gg;
            }
            cv[f] = c;
            hv[f] = og * tanh_(c);
        }

        if (!LAST) {
            float4* cd = (float4*)&g_c[pix * F_];
            cd[0] = make_float4(cv[0], cv[1], cv[2], cv[3]);
            cd[1] = make_float4(cv[4], cv[5], cv[6], cv[7]);
            float4* hd = (float4*)(h_out + pix * F_);
            hd[0] = make_float4(hv[0], hv[1], hv[2], hv[3]);
            hd[1] = make_float4(hv[4], hv[5], hv[6], hv[7]);
        } else {
            // BN (inference, eps=1e-3) + LeakyReLU(0.3) + Dense(2)
            float o0 = db[0], o1 = db[1];
#pragma unroll
            for (int f = 0; f < F_; f++) {
                float xn = (hv[f] - mean[f]) * rsqrtf(var[f] + 1e-3f) * gamma[f] + beta[f];
                xn = (xn >= 0.f) ? xn : 0.3f * xn;
                o0 += xn * dw[2 * f + 0];
                o1 += xn * dw[2 * f + 1];
            }
            *(float2*)(out + pix * 2) = make_float2(o0, o1);
        }
    }
}

extern "C" void kernel_launch(void* const* d_in, const int* in_sizes, int n_in,
                              void* d_out, int out_size)
{
    (void)in_sizes; (void)n_in; (void)out_size;
    const float* x     = (const float*)d_in[0];
    const float* wk    = (const float*)d_in[1];
    const float* wr    = (const float*)d_in[2];
    const float* bias  = (const float*)d_in[3];
    const float* gamma = (const float*)d_in[4];
    const float* beta  = (const float*)d_in[5];
    const float* mean  = (const float*)d_in[6];
    const float* var   = (const float*)d_in[7];
    const float* dw    = (const float*)d_in[8];
    const float* db    = (const float*)d_in[9];
    float* out         = (float*)d_out;

    float *h0 = nullptr, *h1 = nullptr;
    cudaGetSymbolAddress((void**)&h0, g_h0);
    cudaGetSymbolAddress((void**)&h1, g_h1);

    dim3 grid(W_ / TXD, H_ / TILEY, B_);   // (8, 16, 16) = 2048 blocks
    dim3 block(TXD, TYD, 1);               // 256 threads, warp = one 32-wide row

    // t=0: h=c=0 (FIRST), writes h0 + c
    convlstm_step<true,  false><<<grid, block>>>(x, 0, wk, wr, bias, h0, h0,
                                                 gamma, beta, mean, var, dw, db, out);
    // t=1..3: ping-pong h buffers, c in place
    convlstm_step<false, false><<<grid, block>>>(x, 1, wk, wr, bias, h0, h1,
                                                 gamma, beta, mean, var, dw, db, out);
    convlstm_step<false, false><<<grid, block>>>(x, 2, wk, wr, bias, h1, h0,
                                                 gamma, beta, mean, var, dw, db, out);
    convlstm_step<false, false><<<grid, block>>>(x, 3, wk, wr, bias, h0, h1,
                                                 gamma, beta, mean, var, dw, db, out);
    // t=4: LAST — fused BN + LeakyReLU + Dense epilogue straight to d_out
    convlstm_step<false, true ><<<grid, block>>>(x, 4, wk, wr, bias, h1, h1,
                                                 gamma, beta, mean, var, dw, db, out);
}